// round 4
// baseline (speedup 1.0000x reference)
#include <cuda_runtime.h>

// ---------------------------------------------------------------------------
// Compile-time G(3,0,1) blade algebra (verified: rel_err 8.5e-8).
// Basis order: 0:1 1:e0 2:e1 3:e2 4:e3 5:e01 6:e02 7:e03 8:e12 9:e13 10:e23
//              11:e012 12:e013 13:e023 14:e123 15:e0123
// ---------------------------------------------------------------------------

namespace ga {

__host__ __device__ constexpr int mask_of(int i) {
    const int t[16] = {0, 1, 2, 4, 8, 3, 5, 9, 6, 10, 12, 7, 11, 13, 14, 15};
    return t[i];
}
__host__ __device__ constexpr int idx_of(int m) {
    const int t[16] = {0, 1, 2, 5, 3, 6, 8, 11, 4, 7, 9, 12, 10, 13, 14, 15};
    return t[m];
}
__host__ __device__ constexpr int popc4(int m) {
    return (m & 1) + ((m >> 1) & 1) + ((m >> 2) & 1) + ((m >> 3) & 1);
}
__host__ __device__ constexpr int rsign(int a, int b) {
    int cnt = 0;
    for (int i = 1; i < 4; ++i)
        if ((a >> i) & 1) cnt += popc4(b & ((1 << i) - 1));
    return (cnt & 1) ? -1 : 1;
}

__host__ __device__ constexpr int gp_coef(int k, int j) {
    const int mk = mask_of(k), mj = mask_of(j);
    const int mi = mk ^ mj;
    if (mi & mj & 1) return 0;              // shared e0 -> metric 0
    return rsign(mi, mj);
}
__host__ __device__ constexpr int gp_src(int k, int j) {
    return idx_of(mask_of(k) ^ mask_of(j));
}

__host__ __device__ constexpr int jn_coef(int k, int j) {
    const int mk = mask_of(k), mj = mask_of(j);
    const int nmj = ~mj & 15;
    if (mk & nmj) return 0;                 // requires mk subset of mj
    const int mi = mk | nmj;
    return rsign(~mk & 15, mk)
         * rsign(mi, ~mi & 15)
         * rsign(mj, ~mj & 15)
         * rsign(~mi & 15, nmj);
}
__host__ __device__ constexpr int jn_src(int k, int j) {
    const int mk = mask_of(k), mj = mask_of(j);
    return idx_of(mk | (~mj & 15));
}

// -------- compile-time unrolled accumulators (literal register indices) ----

template <int K, int J>
__device__ __forceinline__ float gp_term(const float (&x)[16], const float (&y)[16]) {
    if constexpr (J >= 16) {
        return 0.0f;
    } else {
        float acc = gp_term<K, J + 1>(x, y);
        constexpr int c = gp_coef(K, J);
        constexpr int p = gp_src(K, J);
        if constexpr (c == 1)  acc = fmaf(x[p], y[J], acc);
        if constexpr (c == -1) acc = fmaf(-x[p], y[J], acc);
        return acc;
    }
}

template <int K, int J>
__device__ __forceinline__ float jn_term(const float (&x)[16], const float (&y)[16]) {
    if constexpr (J >= 16) {
        return 0.0f;
    } else {
        float acc = jn_term<K, J + 1>(x, y);
        constexpr int c = jn_coef(K, J);
        constexpr int p = jn_src(K, J);
        if constexpr (c == 1)  acc = fmaf(x[p], y[J], acc);
        if constexpr (c == -1) acc = fmaf(-x[p], y[J], acc);
        return acc;
    }
}

template <int K>
__device__ __forceinline__ float4 gp_quad(const float (&x)[16], const float (&y)[16]) {
    return make_float4(gp_term<K + 0, 0>(x, y), gp_term<K + 1, 0>(x, y),
                       gp_term<K + 2, 0>(x, y), gp_term<K + 3, 0>(x, y));
}

template <int K>
__device__ __forceinline__ float4 jn_quad(const float (&x)[16], const float (&y)[16],
                                          float r15) {
    return make_float4(r15 * jn_term<K + 0, 0>(x, y), r15 * jn_term<K + 1, 0>(x, y),
                       r15 * jn_term<K + 2, 0>(x, y), r15 * jn_term<K + 3, 0>(x, y));
}

}  // namespace ga

// ---------------------------------------------------------------------------
// Persistent grid-stride kernel with one-deep register prefetch pipeline.
// Loads for point p+stride are issued before computing point p, so every
// warp keeps ~4.25KB of DRAM traffic in flight continuously instead of only
// during a one-shot load phase. Single wave: 148*3 CTAs, ~4.6 iters/thread.
// ---------------------------------------------------------------------------

__device__ __forceinline__ void unpack(const float4 (&v)[4], float (&s)[16]) {
#pragma unroll
    for (int q = 0; q < 4; ++q) {
        s[4 * q + 0] = v[q].x; s[4 * q + 1] = v[q].y;
        s[4 * q + 2] = v[q].z; s[4 * q + 3] = v[q].w;
    }
}

__device__ __forceinline__ void compute_store(const float4 (&cx)[4], const float4 (&cy)[4],
                                              float cr, float4* __restrict__ outp) {
    float x[16], y[16];
    unpack(cx, x);
    unpack(cy, y);
    __stcs(outp + 0, ga::gp_quad<0>(x, y));
    __stcs(outp + 1, ga::gp_quad<4>(x, y));
    __stcs(outp + 2, ga::gp_quad<8>(x, y));
    __stcs(outp + 3, ga::gp_quad<12>(x, y));
    __stcs(outp + 4, ga::jn_quad<0>(x, y, cr));
    __stcs(outp + 5, ga::jn_quad<4>(x, y, cr));
    __stcs(outp + 6, ga::jn_quad<8>(x, y, cr));
    __stcs(outp + 7, ga::jn_quad<12>(x, y, cr));
}

__global__ __launch_bounds__(256, 3)
void MVGeometricBilinear_kernel(const float4* __restrict__ x4,
                                const float4* __restrict__ y4,
                                const float* __restrict__ ref,
                                float4* __restrict__ o4,
                                int npts) {
    const int stride = gridDim.x * blockDim.x;
    int p = blockIdx.x * blockDim.x + threadIdx.x;
    if (p >= npts) return;

    // prologue: load point p
    float4 cx[4], cy[4];
    float cr;
#pragma unroll
    for (int q = 0; q < 4; ++q) {
        cx[q] = __ldcs(x4 + p * 4 + q);
        cy[q] = __ldcs(y4 + p * 4 + q);
    }
    cr = __ldcs(ref + p * 16 + 15);

#pragma unroll 2
    while (true) {
        const int pn = p + stride;
        if (pn < npts) {
            // issue next point's loads (independent of current compute)
            float4 nx[4], ny[4];
            float nr;
#pragma unroll
            for (int q = 0; q < 4; ++q) {
                nx[q] = __ldcs(x4 + pn * 4 + q);
                ny[q] = __ldcs(y4 + pn * 4 + q);
            }
            nr = __ldcs(ref + pn * 16 + 15);

            compute_store(cx, cy, cr, o4 + p * 8);

            // rotate buffers (vanishes under unroll-2 register renaming)
#pragma unroll
            for (int q = 0; q < 4; ++q) { cx[q] = nx[q]; cy[q] = ny[q]; }
            cr = nr;
            p = pn;
        } else {
            compute_store(cx, cy, cr, o4 + p * 8);
            break;
        }
    }
}

extern "C" void kernel_launch(void* const* d_in, const int* in_sizes, int n_in,
                              void* d_out, int out_size) {
    const float* x   = (const float*)d_in[0];
    const float* y   = (const float*)d_in[1];
    const float* ref = (const float*)d_in[2];
    float* out       = (float*)d_out;

    const int npts = in_sizes[0] / 16;
    const int threads = 256;
    // single balanced wave: 148 SMs * 3 CTAs/SM
    int blocks = 148 * 3;
    const int max_blocks = (npts + threads - 1) / threads;
    if (blocks > max_blocks) blocks = max_blocks;

    MVGeometricBilinear_kernel<<<blocks, threads>>>(
        (const float4*)x, (const float4*)y, ref, (float4*)out, npts);
}